// round 1
// baseline (speedup 1.0000x reference)
#include <cuda_runtime.h>
#include <math.h>

#define B_TOTAL 65536

// Scratch (no cudaMalloc allowed): intermediate activations.
__device__ float g_pool1[B_TOTAL * 288];  // [B,2,12,12] after conv1+relu+pool
__device__ float g_flat [B_TOTAL * 256];  // [B,16,4,4]  after conv2+relu+pool (flattened)

// ---------------------------------------------------------------------------
// Kernel 1: conv1 (5x5, 1->2 ch) + bias + relu + maxpool2
// x: [B,1,28,28] -> g_pool1: [B,2,12,12]
// 4 samples/block, 96 threads/sample: (co in 0..1) x (py in 0..11) x (pxh in 0..3)
// Each thread produces 3 pooled outputs (px = pxh*3 .. pxh*3+2).
// ---------------------------------------------------------------------------
__global__ void __launch_bounds__(384) k_conv1(const float* __restrict__ x,
                                               const float* __restrict__ w1,
                                               const float* __restrict__ b1) {
    __shared__ float s_in[4 * 784];
    const int t = threadIdx.x;
    const long b0 = (long)blockIdx.x * 4;

    for (int i = t; i < 4 * 784; i += 384)
        s_in[i] = x[b0 * 784 + i];

    const int sl  = t / 96;
    const int idx = t % 96;
    const int co  = idx / 48;
    const int rem = idx % 48;
    const int py  = rem >> 2;
    const int pxh = rem & 3;

    float w[25];
#pragma unroll
    for (int i = 0; i < 25; i++) w[i] = __ldg(&w1[co * 25 + i]);
    const float bias = __ldg(&b1[co]);

    __syncthreads();

    const float* in = &s_in[sl * 784];
    const int c0 = pxh * 6;   // first input column needed
    const int y0 = py * 2;    // first conv row

    float acc[2][6];
#pragma unroll
    for (int yy = 0; yy < 2; yy++)
#pragma unroll
        for (int cx = 0; cx < 6; cx++) acc[yy][cx] = 0.f;

#pragma unroll
    for (int iy = 0; iy < 6; iy++) {
        float row[10];
#pragma unroll
        for (int c = 0; c < 10; c++) row[c] = in[(y0 + iy) * 28 + c0 + c];
#pragma unroll
        for (int yy = 0; yy < 2; yy++) {
            const int ky = iy - yy;
            if (ky >= 0 && ky < 5) {
#pragma unroll
                for (int cx = 0; cx < 6; cx++)
#pragma unroll
                    for (int kx = 0; kx < 5; kx++)
                        acc[yy][cx] = fmaf(row[cx + kx], w[ky * 5 + kx], acc[yy][cx]);
            }
        }
    }

    const long b = b0 + sl;
    float* op = &g_pool1[b * 288 + co * 144 + py * 12 + pxh * 3];
#pragma unroll
    for (int px = 0; px < 3; px++) {
        float v = fmaxf(fmaxf(acc[0][2 * px], acc[0][2 * px + 1]),
                        fmaxf(acc[1][2 * px], acc[1][2 * px + 1]));
        op[px] = fmaxf(v + bias, 0.f);  // relu(max+b) == max(relu) since bias uniform
    }
}

// ---------------------------------------------------------------------------
// Kernel 2: conv2 (5x5, 2->16 ch) + bias + relu + maxpool2
// g_pool1 [B,2,12,12] -> g_flat [B,256]  (layout c*16 + y*4 + x, matches reshape)
// 256 threads = 4 samples x 64 (co 0..15, py 0..3); 8 iterations => 32 samples/block.
// Each thread produces 4 pooled outputs (full px row) -> float4 store.
// ---------------------------------------------------------------------------
__global__ void __launch_bounds__(256) k_conv2(const float* __restrict__ w2,
                                               const float* __restrict__ b2) {
    __shared__ float s_in[4][288];
    const int t  = threadIdx.x;
    const int sl = t >> 6;
    const int idx = t & 63;
    const int co = idx >> 2;
    const int py = idx & 3;

    float w[2][25];
#pragma unroll
    for (int ci = 0; ci < 2; ci++)
#pragma unroll
        for (int i = 0; i < 25; i++) w[ci][i] = __ldg(&w2[(co * 2 + ci) * 25 + i]);
    const float bias = __ldg(&b2[co]);

    const long bbase = (long)blockIdx.x * 32;

    for (int it = 0; it < 8; it++) {
        __syncthreads();
        for (int i = t; i < 4 * 288; i += 256)
            (&s_in[0][0])[i] = g_pool1[bbase * 288 + (long)it * (4 * 288) + i];
        __syncthreads();

        const float* in = s_in[sl];
        float acc[2][8];
#pragma unroll
        for (int yy = 0; yy < 2; yy++)
#pragma unroll
            for (int xx = 0; xx < 8; xx++) acc[yy][xx] = 0.f;

#pragma unroll
        for (int ci = 0; ci < 2; ci++) {
#pragma unroll
            for (int iy = 0; iy < 6; iy++) {
                float row[12];
#pragma unroll
                for (int c = 0; c < 12; c++)
                    row[c] = in[ci * 144 + (2 * py + iy) * 12 + c];
#pragma unroll
                for (int yy = 0; yy < 2; yy++) {
                    const int ky = iy - yy;
                    if (ky >= 0 && ky < 5) {
#pragma unroll
                        for (int xx = 0; xx < 8; xx++)
#pragma unroll
                            for (int kx = 0; kx < 5; kx++)
                                acc[yy][xx] = fmaf(row[xx + kx], w[ci][ky * 5 + kx], acc[yy][xx]);
                    }
                }
            }
        }

        float4 o;
        float* po = (float*)&o;
#pragma unroll
        for (int px = 0; px < 4; px++) {
            float v = fmaxf(fmaxf(acc[0][2 * px], acc[0][2 * px + 1]),
                            fmaxf(acc[1][2 * px], acc[1][2 * px + 1]));
            po[px] = fmaxf(v + bias, 0.f);
        }
        const long b = bbase + it * 4 + sl;
        *(float4*)&g_flat[b * 256 + co * 16 + py * 4] = o;
    }
}

// ---------------------------------------------------------------------------
// Kernel 3: fc1(256->64,relu) + fc2(64->2) + quantum(2 qubits) + fc3 + log_softmax
// Warp = 32 samples. Lane layout: lane = sg*8 + og (sg 0..3 samples-group, og 0..7
// output-group). Lane tile: 8 samples (sg*8+j) x 8 outputs (og*8+oo).
// fc1 inner loop uses fma.rn.f32x2 (even/odd-k dual accumulation, no packing).
// ---------------------------------------------------------------------------
__device__ __forceinline__ void ldg_2u64(const void* p, unsigned long long& a,
                                         unsigned long long& b) {
    asm volatile("ld.global.nc.v2.u64 {%0,%1}, [%2];" : "=l"(a), "=l"(b) : "l"(p));
}
__device__ __forceinline__ void ffma2(unsigned long long& d, unsigned long long a,
                                      unsigned long long b) {
    asm("fma.rn.f32x2 %0, %1, %2, %0;" : "+l"(d) : "l"(a), "l"(b));
}
__device__ __forceinline__ float2 u2f2(unsigned long long v) {
    float2 r;
    asm("mov.b64 {%0,%1}, %2;" : "=f"(r.x), "=f"(r.y) : "l"(v));
    return r;
}

__global__ void __launch_bounds__(128) k_fc(const float* __restrict__ fc1w,
                                            const float* __restrict__ fc1b,
                                            const float* __restrict__ fc2w,
                                            const float* __restrict__ fc2b,
                                            const float* __restrict__ fc3w,
                                            const float* __restrict__ fc3b,
                                            const float* __restrict__ qp,
                                            float* __restrict__ out) {
    const int warp = threadIdx.x >> 5, lane = threadIdx.x & 31;
    const int og = lane & 7, sg = lane >> 3;
    const long b0 = ((long)blockIdx.x * 4 + warp) * 32;

    const char* hbase = (const char*)&g_flat[(b0 + (long)sg * 8) * 256];
    const char* wbase = (const char*)&fc1w[og * 8 * 256];

    unsigned long long acc[8][8];
#pragma unroll
    for (int j = 0; j < 8; j++)
#pragma unroll
        for (int oo = 0; oo < 8; oo++) acc[j][oo] = 0ULL;

#pragma unroll 2
    for (int kk = 0; kk < 64; kk++) {
        unsigned long long wlo[8], whi[8];
#pragma unroll
        for (int oo = 0; oo < 8; oo++)
            ldg_2u64(wbase + oo * 1024 + kk * 16, wlo[oo], whi[oo]);
#pragma unroll
        for (int j = 0; j < 8; j++) {
            unsigned long long hlo, hhi;
            ldg_2u64(hbase + j * 1024 + kk * 16, hlo, hhi);
#pragma unroll
            for (int oo = 0; oo < 8; oo++) {
                ffma2(acc[j][oo], hlo, wlo[oo]);
                ffma2(acc[j][oo], hhi, whi[oo]);
            }
        }
    }

    // bias + relu + fc2 partial sums over this lane's 8 outputs
    float p0[8], p1[8];
#pragma unroll
    for (int j = 0; j < 8; j++) { p0[j] = 0.f; p1[j] = 0.f; }
#pragma unroll
    for (int oo = 0; oo < 8; oo++) {
        const int o = og * 8 + oo;
        const float bb  = __ldg(&fc1b[o]);
        const float w20 = __ldg(&fc2w[o]);
        const float w21 = __ldg(&fc2w[64 + o]);
#pragma unroll
        for (int j = 0; j < 8; j++) {
            float2 v2 = u2f2(acc[j][oo]);
            float v = fmaxf(v2.x + v2.y + bb, 0.f);
            p0[j] = fmaf(v, w20, p0[j]);
            p1[j] = fmaf(v, w21, p1[j]);
        }
    }
    // reduce across the 8 og-lanes of each sg group (butterfly)
#pragma unroll
    for (int d = 1; d < 8; d <<= 1) {
#pragma unroll
        for (int j = 0; j < 8; j++) {
            p0[j] += __shfl_xor_sync(0xffffffffu, p0[j], d);
            p1[j] += __shfl_xor_sync(0xffffffffu, p1[j], d);
        }
    }
    // lane (sg,og) takes sample j = og  ->  global sample b0 + lane
    float x0 = 0.f, x1 = 0.f;
#pragma unroll
    for (int j = 0; j < 8; j++)
        if (og == j) { x0 = p0[j]; x1 = p1[j]; }
    x0 += __ldg(&fc2b[0]);
    x1 += __ldg(&fc2b[1]);

    // ---- quantum circuit (2 qubits, closed-form state after encoding) ----
    float cq[8], sq[8];
#pragma unroll
    for (int i = 0; i < 8; i++) {
        float p = __ldg(&qp[i]);
        sincosf(p, &sq[i], &cq[i]);
    }
    const float PI = 3.14159265358979323846f;
    const float ang = (PI - x0) * (PI - x1);
    const float P = x0 + x1, M = x0 - x1;
    float sPp, cPp, sPm, cPm, sMp, cMp, sMm, cMm;
    sincosf(P + ang, &sPp, &cPp);
    sincosf(P - ang, &sPm, &cPm);
    sincosf(M + ang, &sMp, &cMp);
    sincosf(M - ang, &sMm, &cMm);
    // state after encoding + both CNOTs + ZZ phase:
    // s00 = .5 e^{-i(P+ang)}, s01 = .5 e^{i(ang-M)}, s10 = .5 e^{i(M+ang)}, s11 = .5 e^{i(P-ang)}
    float r00 =  0.5f * cPp, i00 = -0.5f * sPp;
    float r01 =  0.5f * cMm, i01 = -0.5f * sMm;
    float r10 =  0.5f * cMp, i10 =  0.5f * sMp;
    float r11 =  0.5f * cPm, i11 =  0.5f * sPm;

#define ROT0(ii) { float c = cq[ii], s = sq[ii], a, bt;                      \
    a = r00; bt = r10; r00 = c*a - s*bt; r10 = s*a + c*bt;                   \
    a = i00; bt = i10; i00 = c*a - s*bt; i10 = s*a + c*bt;                   \
    a = r01; bt = r11; r01 = c*a - s*bt; r11 = s*a + c*bt;                   \
    a = i01; bt = i11; i01 = c*a - s*bt; i11 = s*a + c*bt; }
#define ROT1(ii) { float c = cq[ii], s = sq[ii], a, bt;                      \
    a = r00; bt = r01; r00 = c*a - s*bt; r01 = s*a + c*bt;                   \
    a = i00; bt = i01; i00 = c*a - s*bt; i01 = s*a + c*bt;                   \
    a = r10; bt = r11; r10 = c*a - s*bt; r11 = s*a + c*bt;                   \
    a = i10; bt = i11; i10 = c*a - s*bt; i11 = s*a + c*bt; }
#define CN01 { float tt; tt = r10; r10 = r11; r11 = tt; tt = i10; i10 = i11; i11 = tt; }
#define CN10 { float tt; tt = r01; r01 = r11; r11 = tt; tt = i01; i01 = i11; i11 = tt; }

    ROT0(0); ROT1(1); CN01;
    ROT0(2); ROT1(3); CN10;
    ROT0(4); ROT1(5); CN01;
    ROT0(6); ROT1(7);

    const float q = (r00 * r00 + i00 * i00) - (r01 * r01 + i01 * i01)
                  - (r10 * r10 + i10 * i10) + (r11 * r11 + i11 * i11);

    const float y  = fmaf(q, __ldg(&fc3w[0]), __ldg(&fc3b[0]));
    const float l0 = y, l1 = 1.0f - y;
    const float m  = fmaxf(l0, l1);
    const float lse = m + logf(expf(l0 - m) + expf(l1 - m));

    float2 res;
    res.x = l0 - lse;
    res.y = l1 - lse;
    ((float2*)out)[b0 + lane] = res;
}

// ---------------------------------------------------------------------------
extern "C" void kernel_launch(void* const* d_in, const int* in_sizes, int n_in,
                              void* d_out, int out_size) {
    const float* x   = (const float*)d_in[0];
    const float* c1w = (const float*)d_in[1];
    const float* c1b = (const float*)d_in[2];
    const float* c2w = (const float*)d_in[3];
    const float* c2b = (const float*)d_in[4];
    const float* f1w = (const float*)d_in[5];
    const float* f1b = (const float*)d_in[6];
    const float* f2w = (const float*)d_in[7];
    const float* f2b = (const float*)d_in[8];
    const float* f3w = (const float*)d_in[9];
    const float* f3b = (const float*)d_in[10];
    const float* qp  = (const float*)d_in[11];
    float* out = (float*)d_out;

    k_conv1<<<B_TOTAL / 4, 384>>>(x, c1w, c1b);
    k_conv2<<<B_TOTAL / 32, 256>>>(c2w, c2b);
    k_fc<<<B_TOTAL / 128, 128>>>(f1w, f1b, f2w, f2b, f3w, f3b, qp, out);
}

// round 2
// speedup vs baseline: 1.1675x; 1.1675x over previous
#include <cuda_runtime.h>
#include <math.h>

#define B_TOTAL 65536
typedef unsigned long long ull;

// Scratch: conv output activations (fc input), layout [B][256] float.
__device__ float g_flat[B_TOTAL * 256];

// ---- f32x2 helpers -------------------------------------------------------
__device__ __forceinline__ ull pack2(float a, float b) {
    ull r; asm("mov.b64 %0, {%1,%2};" : "=l"(r) : "f"(a), "f"(b)); return r;
}
__device__ __forceinline__ void unpk(ull v, float& a, float& b) {
    asm("mov.b64 {%0,%1}, %2;" : "=f"(a), "=f"(b) : "l"(v));
}
__device__ __forceinline__ void ffma2(ull& d, ull a, ull b) {
    asm("fma.rn.f32x2 %0, %1, %2, %0;" : "+l"(d) : "l"(a), "l"(b));
}
__device__ __forceinline__ ull add2(ull a, ull b) {
    ull r; asm("add.rn.f32x2 %0, %1, %2;" : "=l"(r) : "l"(a), "l"(b)); return r;
}

// ---------------------------------------------------------------------------
// Fused conv kernel. One block = 2 samples (a "pair"), 256 threads.
// All activations live in smem as (sampleA, sampleB) f32x2 pairs -> every
// LDS.64 is a ready f32x2 operand, every fma.rn.f32x2 does 2 samples at once.
//   stage:  x[2][784] -> sx[784] interleaved
//   phase1: conv1(5x5,1->2)+relu+pool -> sp1[288] (= [2co][12][12] pairs)
//   phase2: conv2(5x5,2->16)+relu+pool -> g_flat (de-interleaved)
// ---------------------------------------------------------------------------
__global__ void __launch_bounds__(256, 2) k_conv(const float* __restrict__ x,
                                                 const float* __restrict__ w1,
                                                 const float* __restrict__ b1,
                                                 const float* __restrict__ w2,
                                                 const float* __restrict__ b2) {
    __shared__ ull sx[784];
    __shared__ ull sp1[288];
    const int t = threadIdx.x;
    const long b0 = (long)blockIdx.x * 2;

    // ---- stage two samples, interleaved ----
    if (t < 196) {
        float4 a4 = ((const float4*)(x + b0 * 784))[t];
        float4 c4 = ((const float4*)(x + (b0 + 1) * 784))[t];
        sx[4 * t + 0] = pack2(a4.x, c4.x);
        sx[4 * t + 1] = pack2(a4.y, c4.y);
        sx[4 * t + 2] = pack2(a4.z, c4.z);
        sx[4 * t + 3] = pack2(a4.w, c4.w);
    }

    // ---- phase 1: conv1 + relu + pool ----
    // task space: 288 tasks = (py*12+px)*2 + co ; thread t does t and t+256.
    // co = t & 1 is invariant across the two tasks -> fixed weight registers.
    {
        const int co1 = t & 1;
        ull wd1[25];
#pragma unroll
        for (int i = 0; i < 25; i++) {
            float w = __ldg(&w1[co1 * 25 + i]);
            wd1[i] = pack2(w, w);
        }
        const float bias1 = __ldg(&b1[co1]);

        __syncthreads();

        for (int task = t; task < 288; task += 256) {
            const int idx = task >> 1;        // py*12 + px
            const int py = idx / 12;
            const int px = idx - py * 12;
            const ull* in = &sx[(2 * py) * 28 + 2 * px];

            ull acc[2][2] = {{0ULL, 0ULL}, {0ULL, 0ULL}};
#pragma unroll
            for (int iy = 0; iy < 6; iy++) {
                ull row[6];
#pragma unroll
                for (int c = 0; c < 6; c++) row[c] = in[iy * 28 + c];
#pragma unroll
                for (int yy = 0; yy < 2; yy++) {
                    const int ky = iy - yy;
                    if (ky >= 0 && ky < 5) {
#pragma unroll
                        for (int xx = 0; xx < 2; xx++)
#pragma unroll
                            for (int kx = 0; kx < 5; kx++)
                                ffma2(acc[yy][xx], row[xx + kx], wd1[ky * 5 + kx]);
                    }
                }
            }
            float a0, a1, e0, e1, c0, c1, d0, d1;
            unpk(acc[0][0], a0, a1); unpk(acc[0][1], e0, e1);
            unpk(acc[1][0], c0, c1); unpk(acc[1][1], d0, d1);
            const float vA = fmaxf(fmaxf(fmaxf(a0, e0), fmaxf(c0, d0)) + bias1, 0.f);
            const float vB = fmaxf(fmaxf(fmaxf(a1, e1), fmaxf(c1, d1)) + bias1, 0.f);
            sp1[co1 * 144 + idx] = pack2(vA, vB);
        }
    }

    // ---- phase 2: conv2 + relu + pool ----
    // t = co*16 + ci*8 + py*2 + pxh  (co 0..15, ci 0..1, py 0..3, pxh 0..1)
    const int co  = t >> 4;
    const int ci  = (t >> 3) & 1;
    const int py  = (t >> 1) & 3;
    const int pxh = t & 1;

    ull wd2[25];
#pragma unroll
    for (int i = 0; i < 25; i++) {
        float w = __ldg(&w2[(co * 2 + ci) * 25 + i]);
        wd2[i] = pack2(w, w);
    }
    const float bias2 = __ldg(&b2[co]);

    __syncthreads();

    const ull* in2 = &sp1[ci * 144 + (2 * py) * 12 + 4 * pxh];
    ull acc[2][4] = {{0, 0, 0, 0}, {0, 0, 0, 0}};
#pragma unroll
    for (int iy = 0; iy < 6; iy++) {
        ull row[8];
#pragma unroll
        for (int c = 0; c < 8; c++) row[c] = in2[iy * 12 + c];
#pragma unroll
        for (int yy = 0; yy < 2; yy++) {
            const int ky = iy - yy;
            if (ky >= 0 && ky < 5) {
#pragma unroll
                for (int xx = 0; xx < 4; xx++)
#pragma unroll
                    for (int kx = 0; kx < 5; kx++)
                        ffma2(acc[yy][xx], row[xx + kx], wd2[ky * 5 + kx]);
            }
        }
    }

    // reduce over ci (partner = t ^ 8)
#pragma unroll
    for (int yy = 0; yy < 2; yy++)
#pragma unroll
        for (int xx = 0; xx < 4; xx++) {
            ull o = __shfl_xor_sync(0xffffffffu, acc[yy][xx], 8);
            acc[yy][xx] = add2(acc[yy][xx], o);
        }

    if (ci == 0) {
        float oA[2], oB[2];
#pragma unroll
        for (int p = 0; p < 2; p++) {
            float a0, a1, e0, e1, c0, c1, d0, d1;
            unpk(acc[0][2 * p],     a0, a1);
            unpk(acc[0][2 * p + 1], e0, e1);
            unpk(acc[1][2 * p],     c0, c1);
            unpk(acc[1][2 * p + 1], d0, d1);
            oA[p] = fmaxf(fmaxf(fmaxf(a0, e0), fmaxf(c0, d0)) + bias2, 0.f);
            oB[p] = fmaxf(fmaxf(fmaxf(a1, e1), fmaxf(c1, d1)) + bias2, 0.f);
        }
        const int off = co * 16 + py * 4 + pxh * 2;
        *(float2*)&g_flat[b0 * 256 + off]       = make_float2(oA[0], oA[1]);
        *(float2*)&g_flat[(b0 + 1) * 256 + off] = make_float2(oB[0], oB[1]);
    }
}

// ---------------------------------------------------------------------------
// Kernel 3: fc1(256->64,relu) + fc2(64->2) + quantum + fc3 + log_softmax
// (unchanged from round 1 — warp = 32 samples, f32x2 over even/odd k)
// ---------------------------------------------------------------------------
__device__ __forceinline__ void ldg_2u64(const void* p, ull& a, ull& b) {
    asm volatile("ld.global.nc.v2.u64 {%0,%1}, [%2];" : "=l"(a), "=l"(b) : "l"(p));
}
__device__ __forceinline__ float2 u2f2(ull v) {
    float2 r;
    asm("mov.b64 {%0,%1}, %2;" : "=f"(r.x), "=f"(r.y) : "l"(v));
    return r;
}

__global__ void __launch_bounds__(128) k_fc(const float* __restrict__ fc1w,
                                            const float* __restrict__ fc1b,
                                            const float* __restrict__ fc2w,
                                            const float* __restrict__ fc2b,
                                            const float* __restrict__ fc3w,
                                            const float* __restrict__ fc3b,
                                            const float* __restrict__ qp,
                                            float* __restrict__ out) {
    const int warp = threadIdx.x >> 5, lane = threadIdx.x & 31;
    const int og = lane & 7, sg = lane >> 3;
    const long b0 = ((long)blockIdx.x * 4 + warp) * 32;

    const char* hbase = (const char*)&g_flat[(b0 + (long)sg * 8) * 256];
    const char* wbase = (const char*)&fc1w[og * 8 * 256];

    ull acc[8][8];
#pragma unroll
    for (int j = 0; j < 8; j++)
#pragma unroll
        for (int oo = 0; oo < 8; oo++) acc[j][oo] = 0ULL;

#pragma unroll 2
    for (int kk = 0; kk < 64; kk++) {
        ull wlo[8], whi[8];
#pragma unroll
        for (int oo = 0; oo < 8; oo++)
            ldg_2u64(wbase + oo * 1024 + kk * 16, wlo[oo], whi[oo]);
#pragma unroll
        for (int j = 0; j < 8; j++) {
            ull hlo, hhi;
            ldg_2u64(hbase + j * 1024 + kk * 16, hlo, hhi);
#pragma unroll
            for (int oo = 0; oo < 8; oo++) {
                ffma2(acc[j][oo], hlo, wlo[oo]);
                ffma2(acc[j][oo], hhi, whi[oo]);
            }
        }
    }

    float p0[8], p1[8];
#pragma unroll
    for (int j = 0; j < 8; j++) { p0[j] = 0.f; p1[j] = 0.f; }
#pragma unroll
    for (int oo = 0; oo < 8; oo++) {
        const int o = og * 8 + oo;
        const float bb  = __ldg(&fc1b[o]);
        const float w20 = __ldg(&fc2w[o]);
        const float w21 = __ldg(&fc2w[64 + o]);
#pragma unroll
        for (int j = 0; j < 8; j++) {
            float2 v2 = u2f2(acc[j][oo]);
            float v = fmaxf(v2.x + v2.y + bb, 0.f);
            p0[j] = fmaf(v, w20, p0[j]);
            p1[j] = fmaf(v, w21, p1[j]);
        }
    }
#pragma unroll
    for (int d = 1; d < 8; d <<= 1) {
#pragma unroll
        for (int j = 0; j < 8; j++) {
            p0[j] += __shfl_xor_sync(0xffffffffu, p0[j], d);
            p1[j] += __shfl_xor_sync(0xffffffffu, p1[j], d);
        }
    }
    float x0 = 0.f, x1 = 0.f;
#pragma unroll
    for (int j = 0; j < 8; j++)
        if (og == j) { x0 = p0[j]; x1 = p1[j]; }
    x0 += __ldg(&fc2b[0]);
    x1 += __ldg(&fc2b[1]);

    // ---- quantum circuit (closed form after encoding) ----
    float cq[8], sq[8];
#pragma unroll
    for (int i = 0; i < 8; i++) {
        float p = __ldg(&qp[i]);
        sincosf(p, &sq[i], &cq[i]);
    }
    const float PI = 3.14159265358979323846f;
    const float ang = (PI - x0) * (PI - x1);
    const float P = x0 + x1, M = x0 - x1;
    float sPp, cPp, sPm, cPm, sMp, cMp, sMm, cMm;
    sincosf(P + ang, &sPp, &cPp);
    sincosf(P - ang, &sPm, &cPm);
    sincosf(M + ang, &sMp, &cMp);
    sincosf(M - ang, &sMm, &cMm);
    float r00 =  0.5f * cPp, i00 = -0.5f * sPp;
    float r01 =  0.5f * cMm, i01 = -0.5f * sMm;
    float r10 =  0.5f * cMp, i10 =  0.5f * sMp;
    float r11 =  0.5f * cPm, i11 =  0.5f * sPm;

#define ROT0(ii) { float c = cq[ii], s = sq[ii], a, bt;                      \
    a = r00; bt = r10; r00 = c*a - s*bt; r10 = s*a + c*bt;                   \
    a = i00; bt = i10; i00 = c*a - s*bt; i10 = s*a + c*bt;                   \
    a = r01; bt = r11; r01 = c*a - s*bt; r11 = s*a + c*bt;                   \
    a = i01; bt = i11; i01 = c*a - s*bt; i11 = s*a + c*bt; }
#define ROT1(ii) { float c = cq[ii], s = sq[ii], a, bt;                      \
    a = r00; bt = r01; r00 = c*a - s*bt; r01 = s*a + c*bt;                   \
    a = i00; bt = i01; i00 = c*a - s*bt; i01 = s*a + c*bt;                   \
    a = r10; bt = r11; r10 = c*a - s*bt; r11 = s*a + c*bt;                   \
    a = i10; bt = i11; i10 = c*a - s*bt; i11 = s*a + c*bt; }
#define CN01 { float tt; tt = r10; r10 = r11; r11 = tt; tt = i10; i10 = i11; i11 = tt; }
#define CN10 { float tt; tt = r01; r01 = r11; r11 = tt; tt = i01; i01 = i11; i11 = tt; }

    ROT0(0); ROT1(1); CN01;
    ROT0(2); ROT1(3); CN10;
    ROT0(4); ROT1(5); CN01;
    ROT0(6); ROT1(7);

    const float q = (r00 * r00 + i00 * i00) - (r01 * r01 + i01 * i01)
                  - (r10 * r10 + i10 * i10) + (r11 * r11 + i11 * i11);

    const float y  = fmaf(q, __ldg(&fc3w[0]), __ldg(&fc3b[0]));
    const float l0 = y, l1 = 1.0f - y;
    const float m  = fmaxf(l0, l1);
    const float lse = m + logf(expf(l0 - m) + expf(l1 - m));

    float2 res;
    res.x = l0 - lse;
    res.y = l1 - lse;
    ((float2*)out)[b0 + lane] = res;
}

// ---------------------------------------------------------------------------
extern "C" void kernel_launch(void* const* d_in, const int* in_sizes, int n_in,
                              void* d_out, int out_size) {
    const float* x   = (const float*)d_in[0];
    const float* c1w = (const float*)d_in[1];
    const float* c1b = (const float*)d_in[2];
    const float* c2w = (const float*)d_in[3];
    const float* c2b = (const float*)d_in[4];
    const float* f1w = (const float*)d_in[5];
    const float* f1b = (const float*)d_in[6];
    const float* f2w = (const float*)d_in[7];
    const float* f2b = (const float*)d_in[8];
    const float* f3w = (const float*)d_in[9];
    const float* f3b = (const float*)d_in[10];
    const float* qp  = (const float*)d_in[11];
    float* out = (float*)d_out;

    k_conv<<<B_TOTAL / 2, 256>>>(x, c1w, c1b, c2w, c2b);
    k_fc<<<B_TOTAL / 128, 128>>>(f1w, f1b, f2w, f2b, f3w, f3b, qp, out);
}

// round 3
// speedup vs baseline: 1.3600x; 1.1648x over previous
#include <cuda_runtime.h>
#include <math.h>

#define B_TOTAL 65536
typedef unsigned long long ull;

// Scratch: conv output activations (fc input), layout [B][256] float.
__device__ float g_flat[B_TOTAL * 256];

// ---- f32x2 helpers -------------------------------------------------------
__device__ __forceinline__ ull pack2(float a, float b) {
    ull r; asm("mov.b64 %0, {%1,%2};" : "=l"(r) : "f"(a), "f"(b)); return r;
}
__device__ __forceinline__ void unpk(ull v, float& a, float& b) {
    asm("mov.b64 {%0,%1}, %2;" : "=f"(a), "=f"(b) : "l"(v));
}
__device__ __forceinline__ void ffma2(ull& d, ull a, ull b) {
    asm("fma.rn.f32x2 %0, %1, %2, %0;" : "+l"(d) : "l"(a), "l"(b));
}

// ---------------------------------------------------------------------------
// Fused conv kernel. One block = 1 sample-pair, 128 threads.
// Activations in smem as (sampleA, sampleB) f32x2 pairs; every LDS.64 is a
// ready f32x2 operand; every fma.rn.f32x2 does 2 samples at once.
//   phase1: 96 tasks = (co, py, pxh) px-triples -> sp1[288] ([co][12][12] pairs)
//   phase2: 128 tasks = (co, py, pxh) px-pairs, both ci in-thread -> g_flat
// ---------------------------------------------------------------------------
__global__ void __launch_bounds__(128, 8) k_conv(const float* __restrict__ x,
                                                 const float* __restrict__ w1,
                                                 const float* __restrict__ b1,
                                                 const float* __restrict__ w2,
                                                 const float* __restrict__ b2) {
    __shared__ ull sx[784];
    __shared__ ull sp1[288];
    const int t = threadIdx.x;
    const long b0 = (long)blockIdx.x * 2;

    // ---- stage the two samples, interleaved ----
    {
        const float4* A = (const float4*)(x + b0 * 784);
        const float4* C = (const float4*)(x + (b0 + 1) * 784);
        for (int i = t; i < 196; i += 128) {
            float4 a4 = A[i], c4 = C[i];
            sx[4 * i + 0] = pack2(a4.x, c4.x);
            sx[4 * i + 1] = pack2(a4.y, c4.y);
            sx[4 * i + 2] = pack2(a4.z, c4.z);
            sx[4 * i + 3] = pack2(a4.w, c4.w);
        }
    }
    __syncthreads();

    // ---- phase 1: conv1 + relu + pool, 96 tasks, 3 pooled px per task ----
    if (t < 96) {
        const int pxh = t & 3;
        const int py  = (t >> 2) % 12;
        const int co1 = t / 48;

        ull wd1[25];
#pragma unroll
        for (int i = 0; i < 25; i++) {
            float w = __ldg(&w1[co1 * 25 + i]);
            wd1[i] = pack2(w, w);
        }
        const float bias1 = __ldg(&b1[co1]);

        const ull* in = &sx[(2 * py) * 28 + 6 * pxh];
        ull acc[2][6] = {{0,0,0,0,0,0},{0,0,0,0,0,0}};
#pragma unroll
        for (int iy = 0; iy < 6; iy++) {
            ull row[10];
#pragma unroll
            for (int c = 0; c < 10; c++) row[c] = in[iy * 28 + c];
#pragma unroll
            for (int yy = 0; yy < 2; yy++) {
                const int ky = iy - yy;
                if (ky >= 0 && ky < 5) {
#pragma unroll
                    for (int cx = 0; cx < 6; cx++)
#pragma unroll
                        for (int kx = 0; kx < 5; kx++)
                            ffma2(acc[yy][cx], row[cx + kx], wd1[ky * 5 + kx]);
                }
            }
        }
#pragma unroll
        for (int p = 0; p < 3; p++) {
            float a0,a1,e0,e1,c0,c1,d0,d1;
            unpk(acc[0][2*p],   a0,a1); unpk(acc[0][2*p+1], e0,e1);
            unpk(acc[1][2*p],   c0,c1); unpk(acc[1][2*p+1], d0,d1);
            float vA = fmaxf(fmaxf(fmaxf(a0,e0), fmaxf(c0,d0)) + bias1, 0.f);
            float vB = fmaxf(fmaxf(fmaxf(a1,e1), fmaxf(c1,d1)) + bias1, 0.f);
            sp1[co1 * 144 + py * 12 + pxh * 3 + p] = pack2(vA, vB);
        }
    }
    __syncthreads();

    // ---- phase 2: conv2 + relu + pool, 128 tasks, both ci in-thread ----
    {
        const int pxh = t & 1;
        const int py  = (t >> 1) & 3;
        const int co  = t >> 3;
        const float bias2 = __ldg(&b2[co]);

        ull acc[2][4] = {{0,0,0,0},{0,0,0,0}};
#pragma unroll
        for (int ci = 0; ci < 2; ci++) {
            ull wd2[25];
#pragma unroll
            for (int i = 0; i < 25; i++) {
                float w = __ldg(&w2[(co * 2 + ci) * 25 + i]);
                wd2[i] = pack2(w, w);
            }
            const ull* in2 = &sp1[ci * 144 + (2 * py) * 12 + 4 * pxh];
#pragma unroll
            for (int iy = 0; iy < 6; iy++) {
                ull row[8];
#pragma unroll
                for (int c = 0; c < 8; c++) row[c] = in2[iy * 12 + c];
#pragma unroll
                for (int yy = 0; yy < 2; yy++) {
                    const int ky = iy - yy;
                    if (ky >= 0 && ky < 5) {
#pragma unroll
                        for (int xx = 0; xx < 4; xx++)
#pragma unroll
                            for (int kx = 0; kx < 5; kx++)
                                ffma2(acc[yy][xx], row[xx + kx], wd2[ky * 5 + kx]);
                    }
                }
            }
        }

        float oA[2], oB[2];
#pragma unroll
        for (int p = 0; p < 2; p++) {
            float a0,a1,e0,e1,c0,c1,d0,d1;
            unpk(acc[0][2*p],   a0,a1); unpk(acc[0][2*p+1], e0,e1);
            unpk(acc[1][2*p],   c0,c1); unpk(acc[1][2*p+1], d0,d1);
            oA[p] = fmaxf(fmaxf(fmaxf(a0,e0), fmaxf(c0,d0)) + bias2, 0.f);
            oB[p] = fmaxf(fmaxf(fmaxf(a1,e1), fmaxf(c1,d1)) + bias2, 0.f);
        }
        const int off = co * 16 + py * 4 + pxh * 2;
        *(float2*)&g_flat[b0 * 256 + off]       = make_float2(oA[0], oA[1]);
        *(float2*)&g_flat[(b0 + 1) * 256 + off] = make_float2(oB[0], oB[1]);
    }
}

// ---------------------------------------------------------------------------
// k_fc: fc1(256->64,relu) + fc2(64->2) + quantum + fc3 + log_softmax
// Block = 256 threads (8 warps), 128 samples. fc1w staged in smem as ull
// k-pairs, padded rows (stride 129 ull) -> conflict-free LDS.64.
// Lane tile: 4 samples x 8 outputs, acc f32x2 over (even k, odd k).
// Warp covers 16 samples (sg 0..3 x 4) x 64 outputs (og 0..7 x 8).
// ---------------------------------------------------------------------------
__global__ void __launch_bounds__(256) k_fc(const float* __restrict__ fc1w,
                                            const float* __restrict__ fc1b,
                                            const float* __restrict__ fc2w,
                                            const float* __restrict__ fc2b,
                                            const float* __restrict__ fc3w,
                                            const float* __restrict__ fc3b,
                                            const float* __restrict__ qp,
                                            float* __restrict__ out) {
    __shared__ ull s_w[64 * 129];   // [o][kk] k-pairs, row stride 129 (pad)

    const int tid  = threadIdx.x;
    const int warp = tid >> 5, lane = tid & 31;
    const int og = lane & 7, sg = lane >> 3;

    // stage fc1w -> smem as (w[o][2kk], w[o][2kk+1]) ull
    {
        const float2* wsrc = (const float2*)fc1w;   // 8192 float2 = k-pairs
        for (int i = tid; i < 8192; i += 256) {
            float2 v = __ldg(&wsrc[i]);
            s_w[(i >> 7) * 129 + (i & 127)] = pack2(v.x, v.y);
        }
    }
    __syncthreads();

    const long wg = (long)blockIdx.x * 8 + warp;   // global warp id
    const long b0w = wg * 16;                      // 16 samples per warp

    const ull* h0 = (const ull*)&g_flat[(b0w + sg * 4) * 256];  // 128 ull/sample
    const ull* wrow = &s_w[(og * 8) * 129];

    ull acc[4][8];
#pragma unroll
    for (int j = 0; j < 4; j++)
#pragma unroll
        for (int oo = 0; oo < 8; oo++) acc[j][oo] = 0ULL;

#pragma unroll 2
    for (int kk = 0; kk < 128; kk++) {
        ull wv[8];
#pragma unroll
        for (int oo = 0; oo < 8; oo++) wv[oo] = wrow[oo * 129 + kk];
        ull hv[4];
#pragma unroll
        for (int j = 0; j < 4; j++) hv[j] = __ldg(&h0[j * 128 + kk]);
#pragma unroll
        for (int j = 0; j < 4; j++)
#pragma unroll
            for (int oo = 0; oo < 8; oo++)
                ffma2(acc[j][oo], hv[j], wv[oo]);
    }

    // bias + relu + fc2 partials (4 samples)
    float p0[4] = {0,0,0,0}, p1[4] = {0,0,0,0};
#pragma unroll
    for (int oo = 0; oo < 8; oo++) {
        const int o = og * 8 + oo;
        const float bb  = __ldg(&fc1b[o]);
        const float w20 = __ldg(&fc2w[o]);
        const float w21 = __ldg(&fc2w[64 + o]);
#pragma unroll
        for (int j = 0; j < 4; j++) {
            float e, od; unpk(acc[j][oo], e, od);
            float v = fmaxf(e + od + bb, 0.f);
            p0[j] = fmaf(v, w20, p0[j]);
            p1[j] = fmaf(v, w21, p1[j]);
        }
    }
    // reduce over the 8 og-lanes of each sg group
#pragma unroll
    for (int d = 1; d < 8; d <<= 1) {
#pragma unroll
        for (int j = 0; j < 4; j++) {
            p0[j] += __shfl_xor_sync(0xffffffffu, p0[j], d);
            p1[j] += __shfl_xor_sync(0xffffffffu, p1[j], d);
        }
    }
    // lane og<4 takes sample j = og
    float x0 = 0.f, x1 = 0.f;
#pragma unroll
    for (int j = 0; j < 4; j++)
        if (og == j) { x0 = p0[j]; x1 = p1[j]; }
    x0 += __ldg(&fc2b[0]);
    x1 += __ldg(&fc2b[1]);
    if (og >= 4) { x0 = 0.f; x1 = 0.f; }   // keep sincos on fast path

    // ---- quantum circuit (closed form after encoding) ----
    float cq[8], sq[8];
#pragma unroll
    for (int i = 0; i < 8; i++) {
        float p = __ldg(&qp[i]);
        sincosf(p, &sq[i], &cq[i]);
    }
    const float PI = 3.14159265358979323846f;
    const float ang = (PI - x0) * (PI - x1);
    const float P = x0 + x1, M = x0 - x1;
    float sPp, cPp, sPm, cPm, sMp, cMp, sMm, cMm;
    sincosf(P + ang, &sPp, &cPp);
    sincosf(P - ang, &sPm, &cPm);
    sincosf(M + ang, &sMp, &cMp);
    sincosf(M - ang, &sMm, &cMm);
    float r00 =  0.5f * cPp, i00 = -0.5f * sPp;
    float r01 =  0.5f * cMm, i01 = -0.5f * sMm;
    float r10 =  0.5f * cMp, i10 =  0.5f * sMp;
    float r11 =  0.5f * cPm, i11 =  0.5f * sPm;

#define ROT0(ii) { float c = cq[ii], s = sq[ii], a, bt;                      \
    a = r00; bt = r10; r00 = c*a - s*bt; r10 = s*a + c*bt;                   \
    a = i00; bt = i10; i00 = c*a - s*bt; i10 = s*a + c*bt;                   \
    a = r01; bt = r11; r01 = c*a - s*bt; r11 = s*a + c*bt;                   \
    a = i01; bt = i11; i01 = c*a - s*bt; i11 = s*a + c*bt; }
#define ROT1(ii) { float c = cq[ii], s = sq[ii], a, bt;                      \
    a = r00; bt = r01; r00 = c*a - s*bt; r01 = s*a + c*bt;                   \
    a = i00; bt = i01; i00 = c*a - s*bt; i01 = s*a + c*bt;                   \
    a = r10; bt = r11; r10 = c*a - s*bt; r11 = s*a + c*bt;                   \
    a = i10; bt = i11; i10 = c*a - s*bt; i11 = s*a + c*bt; }
#define CN01 { float tt; tt = r10; r10 = r11; r11 = tt; tt = i10; i10 = i11; i11 = tt; }
#define CN10 { float tt; tt = r01; r01 = r11; r11 = tt; tt = i01; i01 = i11; i11 = tt; }

    ROT0(0); ROT1(1); CN01;
    ROT0(2); ROT1(3); CN10;
    ROT0(4); ROT1(5); CN01;
    ROT0(6); ROT1(7);

    const float q = (r00 * r00 + i00 * i00) - (r01 * r01 + i01 * i01)
                  - (r10 * r10 + i10 * i10) + (r11 * r11 + i11 * i11);

    const float y  = fmaf(q, __ldg(&fc3w[0]), __ldg(&fc3b[0]));
    const float l0 = y, l1 = 1.0f - y;
    const float m  = fmaxf(l0, l1);
    const float lse = m + logf(expf(l0 - m) + expf(l1 - m));

    if (og < 4) {
        float2 res;
        res.x = l0 - lse;
        res.y = l1 - lse;
        ((float2*)out)[b0w + sg * 4 + og] = res;
    }
}

// ---------------------------------------------------------------------------
extern "C" void kernel_launch(void* const* d_in, const int* in_sizes, int n_in,
                              void* d_out, int out_size) {
    const float* x   = (const float*)d_in[0];
    const float* c1w = (const float*)d_in[1];
    const float* c1b = (const float*)d_in[2];
    const float* c2w = (const float*)d_in[3];
    const float* c2b = (const float*)d_in[4];
    const float* f1w = (const float*)d_in[5];
    const float* f1b = (const float*)d_in[6];
    const float* f2w = (const float*)d_in[7];
    const float* f2b = (const float*)d_in[8];
    const float* f3w = (const float*)d_in[9];
    const float* f3b = (const float*)d_in[10];
    const float* qp  = (const float*)d_in[11];
    float* out = (float*)d_out;

    k_conv<<<B_TOTAL / 2, 128>>>(x, c1w, c1b, c2w, c2b);
    k_fc<<<B_TOTAL / 128, 256>>>(f1w, f1b, f2w, f2b, f3w, f3b, qp, out);
}

// round 4
// speedup vs baseline: 1.7624x; 1.2960x over previous
#include <cuda_runtime.h>
#include <math.h>

#define B_TOTAL 65536
typedef unsigned long long ull;

// Scratch: conv output activations (fc input), layout [B][256] float.
__device__ float g_flat[B_TOTAL * 256];

// ---- f32x2 helpers -------------------------------------------------------
__device__ __forceinline__ ull pack2(float a, float b) {
    ull r; asm("mov.b64 %0, {%1,%2};" : "=l"(r) : "f"(a), "f"(b)); return r;
}
__device__ __forceinline__ void unpk(ull v, float& a, float& b) {
    asm("mov.b64 {%0,%1}, %2;" : "=f"(a), "=f"(b) : "l"(v));
}
__device__ __forceinline__ void ffma2(ull& d, ull a, ull b) {
    asm("fma.rn.f32x2 %0, %1, %2, %0;" : "+l"(d) : "l"(a), "l"(b));
}

// ---------------------------------------------------------------------------
// Fused conv kernel. One block = 1 sample-pair, 128 threads.
// Activations in smem as (sampleA, sampleB) f32x2 pairs; row loads use
// 16B LDS.128 (ulonglong2) — all bases are even-ull so alignment holds.
// ---------------------------------------------------------------------------
__global__ void __launch_bounds__(128, 8) k_conv(const float* __restrict__ x,
                                                 const float* __restrict__ w1,
                                                 const float* __restrict__ b1,
                                                 const float* __restrict__ w2,
                                                 const float* __restrict__ b2) {
    __shared__ __align__(16) ull sx[784];
    __shared__ __align__(16) ull sp1[288];
    const int t = threadIdx.x;
    const long b0 = (long)blockIdx.x * 2;

    // ---- stage the two samples, interleaved ----
    {
        const float4* A = (const float4*)(x + b0 * 784);
        const float4* C = (const float4*)(x + (b0 + 1) * 784);
        for (int i = t; i < 196; i += 128) {
            float4 a4 = A[i], c4 = C[i];
            sx[4 * i + 0] = pack2(a4.x, c4.x);
            sx[4 * i + 1] = pack2(a4.y, c4.y);
            sx[4 * i + 2] = pack2(a4.z, c4.z);
            sx[4 * i + 3] = pack2(a4.w, c4.w);
        }
    }
    __syncthreads();

    // ---- phase 1: conv1 + relu + pool, 96 tasks, 3 pooled px per task ----
    if (t < 96) {
        const int pxh = t & 3;
        const int py  = (t >> 2) % 12;
        const int co1 = t / 48;

        ull wd1[25];
#pragma unroll
        for (int i = 0; i < 25; i++) {
            float w = __ldg(&w1[co1 * 25 + i]);
            wd1[i] = pack2(w, w);
        }
        const float bias1 = __ldg(&b1[co1]);

        const ull* in = &sx[(2 * py) * 28 + 6 * pxh];   // even ull offset
        ull acc[2][6] = {{0,0,0,0,0,0},{0,0,0,0,0,0}};
#pragma unroll
        for (int iy = 0; iy < 6; iy++) {
            ull row[10];
#pragma unroll
            for (int c = 0; c < 10; c += 2) {
                ulonglong2 v = *(const ulonglong2*)&in[iy * 28 + c];
                row[c] = v.x; row[c + 1] = v.y;
            }
#pragma unroll
            for (int yy = 0; yy < 2; yy++) {
                const int ky = iy - yy;
                if (ky >= 0 && ky < 5) {
#pragma unroll
                    for (int cx = 0; cx < 6; cx++)
#pragma unroll
                        for (int kx = 0; kx < 5; kx++)
                            ffma2(acc[yy][cx], row[cx + kx], wd1[ky * 5 + kx]);
                }
            }
        }
#pragma unroll
        for (int p = 0; p < 3; p++) {
            float a0,a1,e0,e1,c0,c1,d0,d1;
            unpk(acc[0][2*p],   a0,a1); unpk(acc[0][2*p+1], e0,e1);
            unpk(acc[1][2*p],   c0,c1); unpk(acc[1][2*p+1], d0,d1);
            float vA = fmaxf(fmaxf(fmaxf(a0,e0), fmaxf(c0,d0)) + bias1, 0.f);
            float vB = fmaxf(fmaxf(fmaxf(a1,e1), fmaxf(c1,d1)) + bias1, 0.f);
            sp1[co1 * 144 + py * 12 + pxh * 3 + p] = pack2(vA, vB);
        }
    }
    __syncthreads();

    // ---- phase 2: conv2 + relu + pool, 128 tasks, both ci in-thread ----
    {
        const int pxh = t & 1;
        const int py  = (t >> 1) & 3;
        const int co  = t >> 3;
        const float bias2 = __ldg(&b2[co]);

        ull acc[2][4] = {{0,0,0,0},{0,0,0,0}};
#pragma unroll
        for (int ci = 0; ci < 2; ci++) {
            ull wd2[25];
#pragma unroll
            for (int i = 0; i < 25; i++) {
                float w = __ldg(&w2[(co * 2 + ci) * 25 + i]);
                wd2[i] = pack2(w, w);
            }
            const ull* in2 = &sp1[ci * 144 + (2 * py) * 12 + 4 * pxh];  // even
#pragma unroll
            for (int iy = 0; iy < 6; iy++) {
                ull row[8];
#pragma unroll
                for (int c = 0; c < 8; c += 2) {
                    ulonglong2 v = *(const ulonglong2*)&in2[iy * 12 + c];
                    row[c] = v.x; row[c + 1] = v.y;
                }
#pragma unroll
                for (int yy = 0; yy < 2; yy++) {
                    const int ky = iy - yy;
                    if (ky >= 0 && ky < 5) {
#pragma unroll
                        for (int xx = 0; xx < 4; xx++)
#pragma unroll
                            for (int kx = 0; kx < 5; kx++)
                                ffma2(acc[yy][xx], row[xx + kx], wd2[ky * 5 + kx]);
                    }
                }
            }
        }

        float oA[2], oB[2];
#pragma unroll
        for (int p = 0; p < 2; p++) {
            float a0,a1,e0,e1,c0,c1,d0,d1;
            unpk(acc[0][2*p],   a0,a1); unpk(acc[0][2*p+1], e0,e1);
            unpk(acc[1][2*p],   c0,c1); unpk(acc[1][2*p+1], d0,d1);
            oA[p] = fmaxf(fmaxf(fmaxf(a0,e0), fmaxf(c0,d0)) + bias2, 0.f);
            oB[p] = fmaxf(fmaxf(fmaxf(a1,e1), fmaxf(c1,d1)) + bias2, 0.f);
        }
        const int off = co * 16 + py * 4 + pxh * 2;
        *(float2*)&g_flat[b0 * 256 + off]       = make_float2(oA[0], oA[1]);
        *(float2*)&g_flat[(b0 + 1) * 256 + off] = make_float2(oB[0], oB[1]);
    }
}

// ---------------------------------------------------------------------------
// k_fc: fc1(256->64,relu) + fc2(64->2) + quantum + fc3 + log_softmax
// Block = 256 threads (8 warps), 128 samples.
// Weights in smem as s_w[kp*130 + 2*o + b]: kp = k-quad (4 k values = 2 ull),
// b selects the ull. Outputs mapped o = og + 8*oo so the 8 og-lanes of an
// LDS.128 sit at word offsets 4*og mod 32 = all distinct banks (conflict-free).
// Lane tile: 4 samples x 8 outputs; h via __ldg(ulonglong2).
// ---------------------------------------------------------------------------
__global__ void __launch_bounds__(256, 2) k_fc(const float* __restrict__ fc1w,
                                               const float* __restrict__ fc1b,
                                               const float* __restrict__ fc2w,
                                               const float* __restrict__ fc2b,
                                               const float* __restrict__ fc3w,
                                               const float* __restrict__ fc3b,
                                               const float* __restrict__ qp,
                                               float* __restrict__ out) {
    __shared__ __align__(16) ull s_w[64 * 130];   // 66.6 KB

    const int tid  = threadIdx.x;
    const int warp = tid >> 5, lane = tid & 31;
    const int og = lane & 7, sg = lane >> 3;

    // stage fc1w -> smem: wsrc[i] = k-pair (o = i>>7, kk = i&127)
    {
        const float2* wsrc = (const float2*)fc1w;
        for (int i = tid; i < 8192; i += 256) {
            float2 v = __ldg(&wsrc[i]);
            const int o = i >> 7, kk = i & 127;
            s_w[(kk >> 1) * 130 + 2 * o + (kk & 1)] = pack2(v.x, v.y);
        }
    }
    __syncthreads();

    const long wg = (long)blockIdx.x * 8 + warp;   // global warp id
    const long b0w = wg * 16;                      // 16 samples per warp

    const ull* h0 = (const ull*)&g_flat[(b0w + sg * 4) * 256];  // 128 ull/sample
    const ull* wbase = &s_w[2 * og];

    ull acc[4][8];
#pragma unroll
    for (int j = 0; j < 4; j++)
#pragma unroll
        for (int oo = 0; oo < 8; oo++) acc[j][oo] = 0ULL;

    for (int kp = 0; kp < 64; kp++) {
        ull w0[8], w1[8];
#pragma unroll
        for (int oo = 0; oo < 8; oo++) {
            ulonglong2 v = *(const ulonglong2*)&wbase[kp * 130 + 16 * oo];
            w0[oo] = v.x; w1[oo] = v.y;
        }
        ull ha[4], hb[4];
#pragma unroll
        for (int j = 0; j < 4; j++) {
            ulonglong2 hv = __ldg((const ulonglong2*)&h0[j * 128 + 2 * kp]);
            ha[j] = hv.x; hb[j] = hv.y;
        }
#pragma unroll
        for (int j = 0; j < 4; j++)
#pragma unroll
            for (int oo = 0; oo < 8; oo++) {
                ffma2(acc[j][oo], ha[j], w0[oo]);
                ffma2(acc[j][oo], hb[j], w1[oo]);
            }
    }

    // bias + relu + fc2 partials (4 samples); this lane's outputs o = og+8*oo
    float p0[4] = {0,0,0,0}, p1[4] = {0,0,0,0};
#pragma unroll
    for (int oo = 0; oo < 8; oo++) {
        const int o = og + 8 * oo;
        const float bb  = __ldg(&fc1b[o]);
        const float w20 = __ldg(&fc2w[o]);
        const float w21 = __ldg(&fc2w[64 + o]);
#pragma unroll
        for (int j = 0; j < 4; j++) {
            float e, od; unpk(acc[j][oo], e, od);
            float v = fmaxf(e + od + bb, 0.f);
            p0[j] = fmaf(v, w20, p0[j]);
            p1[j] = fmaf(v, w21, p1[j]);
        }
    }
    // reduce over the 8 og-lanes of each sg group
#pragma unroll
    for (int d = 1; d < 8; d <<= 1) {
#pragma unroll
        for (int j = 0; j < 4; j++) {
            p0[j] += __shfl_xor_sync(0xffffffffu, p0[j], d);
            p1[j] += __shfl_xor_sync(0xffffffffu, p1[j], d);
        }
    }
    // lane og<4 takes sample j = og
    float x0 = 0.f, x1 = 0.f;
#pragma unroll
    for (int j = 0; j < 4; j++)
        if (og == j) { x0 = p0[j]; x1 = p1[j]; }
    x0 += __ldg(&fc2b[0]);
    x1 += __ldg(&fc2b[1]);
    if (og >= 4) { x0 = 0.f; x1 = 0.f; }

    // ---- quantum circuit (closed form after encoding) ----
    float cq[8], sq[8];
#pragma unroll
    for (int i = 0; i < 8; i++) {
        float p = __ldg(&qp[i]);
        sincosf(p, &sq[i], &cq[i]);
    }
    const float PI = 3.14159265358979323846f;
    const float ang = (PI - x0) * (PI - x1);
    const float P = x0 + x1, M = x0 - x1;
    float sPp, cPp, sPm, cPm, sMp, cMp, sMm, cMm;
    sincosf(P + ang, &sPp, &cPp);
    sincosf(P - ang, &sPm, &cPm);
    sincosf(M + ang, &sMp, &cMp);
    sincosf(M - ang, &sMm, &cMm);
    float r00 =  0.5f * cPp, i00 = -0.5f * sPp;
    float r01 =  0.5f * cMm, i01 = -0.5f * sMm;
    float r10 =  0.5f * cMp, i10 =  0.5f * sMp;
    float r11 =  0.5f * cPm, i11 =  0.5f * sPm;

#define ROT0(ii) { float c = cq[ii], s = sq[ii], a, bt;                      \
    a = r00; bt = r10; r00 = c*a - s*bt; r10 = s*a + c*bt;                   \
    a = i00; bt = i10; i00 = c*a - s*bt; i10 = s*a + c*bt;                   \
    a = r01; bt = r11; r01 = c*a - s*bt; r11 = s*a + c*bt;                   \
    a = i01; bt = i11; i01 = c*a - s*bt; i11 = s*a + c*bt; }
#define ROT1(ii) { float c = cq[ii], s = sq[ii], a, bt;                      \
    a = r00; bt = r01; r00 = c*a - s*bt; r01 = s*a + c*bt;                   \
    a = i00; bt = i01; i00 = c*a - s*bt; i01 = s*a + c*bt;                   \
    a = r10; bt = r11; r10 = c*a - s*bt; r11 = s*a + c*bt;                   \
    a = i10; bt = i11; i10 = c*a - s*bt; i11 = s*a + c*bt; }
#define CN01 { float tt; tt = r10; r10 = r11; r11 = tt; tt = i10; i10 = i11; i11 = tt; }
#define CN10 { float tt; tt = r01; r01 = r11; r11 = tt; tt = i01; i01 = i11; i11 = tt; }

    ROT0(0); ROT1(1); CN01;
    ROT0(2); ROT1(3); CN10;
    ROT0(4); ROT1(5); CN01;
    ROT0(6); ROT1(7);

    const float q = (r00 * r00 + i00 * i00) - (r01 * r01 + i01 * i01)
                  - (r10 * r10 + i10 * i10) + (r11 * r11 + i11 * i11);

    const float y  = fmaf(q, __ldg(&fc3w[0]), __ldg(&fc3b[0]));
    const float l0 = y, l1 = 1.0f - y;
    const float m  = fmaxf(l0, l1);
    const float lse = m + logf(expf(l0 - m) + expf(l1 - m));

    if (og < 4) {
        float2 res;
        res.x = l0 - lse;
        res.y = l1 - lse;
        ((float2*)out)[b0w + sg * 4 + og] = res;
    }
}

// ---------------------------------------------------------------------------
extern "C" void kernel_launch(void* const* d_in, const int* in_sizes, int n_in,
                              void* d_out, int out_size) {
    const float* x   = (const float*)d_in[0];
    const float* c1w = (const float*)d_in[1];
    const float* c1b = (const float*)d_in[2];
    const float* c2w = (const float*)d_in[3];
    const float* c2b = (const float*)d_in[4];
    const float* f1w = (const float*)d_in[5];
    const float* f1b = (const float*)d_in[6];
    const float* f2w = (const float*)d_in[7];
    const float* f2b = (const float*)d_in[8];
    const float* f3w = (const float*)d_in[9];
    const float* f3b = (const float*)d_in[10];
    const float* qp  = (const float*)d_in[11];
    float* out = (float*)d_out;

    k_conv<<<B_TOTAL / 2, 128>>>(x, c1w, c1b, c2w, c2b);
    k_fc<<<B_TOTAL / 128, 256>>>(f1w, f1b, f2w, f2b, f3w, f3b, qp, out);
}